// round 11
// baseline (speedup 1.0000x reference)
#include <cuda_runtime.h>
#include <cstdint>

#define BATCH 64
#define SEQ   4096
#define LBL   128
#define IGN   (-100)
#define TPB   64                          // tokens per block
#define NBLK  ((BATCH * SEQ) / TPB)       // 4096 blocks
#define BPR   (SEQ / TPB)                 // 64 blocks per batch row

// Statically initialized so the first (correctness) run is valid; the last
// block restores all persistent state after every launch (graph-replay safe).
#define R8 SEQ, SEQ, SEQ, SEQ, SEQ, SEQ, SEQ, SEQ
__device__ int g_first_invalid[BATCH] = {R8, R8, R8, R8, R8, R8, R8, R8};
#undef R8
__device__ float    g_tokloss[BATCH * SEQ];  // overwritten every launch
__device__ float    g_blocksum[NBLK];        // overwritten every launch
__device__ unsigned g_done = 0;              // self-resetting

// Single fused kernel: scan + per-token loss + deferred-mask final reduce.
// 8 tokens per warp (two groups of 4), 8 lanes per token (R7 core loop).
__global__ __launch_bounds__(256) void loss_kernel(
    const float* __restrict__ emit,
    const int*   __restrict__ target,
    float*       __restrict__ out)
{
    const int warp   = threadIdx.x >> 5;
    const int lane   = threadIdx.x & 31;
    const int tg     = lane >> 3;        // token-in-group 0..3
    const int g      = lane & 7;         // lane-in-token 0..7
    const int token0 = blockIdx.x * TPB + warp * 8 + tg;
    const int token1 = token0 + 4;
    const int b      = token0 >> 12;     // whole block is one batch row
    const int s0     = token0 & (SEQ - 1);
    const int s1     = token1 & (SEQ - 1);

    // Targets first (raw, for the fused invalid-scan).
    int t0r = 0, t1r = 0;
    if (g < 4) {
        t0r = target[token0 * 4 + g];
        t1r = target[token1 * 4 + g];
    }

    // 8 independent 16B row loads.
    const float4* row0 = reinterpret_cast<const float4*>(emit + (size_t)token0 * LBL);
    const float4* row1 = reinterpret_cast<const float4*>(emit + (size_t)token1 * LBL);
    const float4 a0 = row0[g],      a1 = row0[8 + g];
    const float4 a2 = row0[16 + g], a3 = row0[24 + g];
    const float4 c0 = row1[g],      c1 = row1[8 + g];
    const float4 c2 = row1[16 + g], c3 = row1[24 + g];

    // Fused invalid detection (one ballot per token pair; atomic never fires
    // unless IGN actually present).
    const unsigned inv0 = __ballot_sync(0xffffffffu, (g < 4) && (t0r == IGN));
    const unsigned inv1 = __ballot_sync(0xffffffffu, (g < 4) && (t1r == IGN));

    // sum_true gathers (L1 hits on the warp's own in-flight lines).
    float st0 = 0.0f, st1 = 0.0f;
    if (g < 4) {
        st0 = __expf(emit[(size_t)token0 * LBL + (t0r & (LBL - 1))]);
        st1 = __expf(emit[(size_t)token1 * LBL + (t1r & (LBL - 1))]);
    }

    float se0 = 0.0f, se1 = 0.0f;
#define PASS(ACC, V)                                                \
    {                                                               \
        const float e0 = __expf(V.x), e1 = __expf(V.y),             \
                    e2 = __expf(V.z), e3 = __expf(V.w);             \
        ACC += (e0 + e1) + (e2 + e3);                               \
    }
    PASS(se0, a0) PASS(se0, a1) PASS(se0, a2) PASS(se0, a3)
    PASS(se1, c0) PASS(se1, c1) PASS(se1, c2) PASS(se1, c3)
#undef PASS

    // Reduce within the 8-lane group (offsets 1,2,4 stay inside the group).
#pragma unroll
    for (int o = 1; o <= 4; o <<= 1) {
        se0 += __shfl_xor_sync(0xffffffffu, se0, o);
        st0 += __shfl_xor_sync(0xffffffffu, st0, o);
        se1 += __shfl_xor_sync(0xffffffffu, se1, o);
        st1 += __shfl_xor_sync(0xffffffffu, st1, o);
    }

    __shared__ float part[32];
    __shared__ bool  amLast;
    if (g == 0) {
        const float l0 = __logf(se0) - __logf(st0);
        const float l1 = __logf(se1) - __logf(st1);
        g_tokloss[token0] = l0;          // unmasked; mask applied in final pass
        g_tokloss[token1] = l1;
        part[warp * 4 + tg] = l0 + l1;
        const unsigned m = 0xFu << (8 * tg);
        if (inv0 & m) atomicMin(&g_first_invalid[b], s0);
        if (inv1 & m) atomicMin(&g_first_invalid[b], s1);
    }
    __syncthreads();

    if (threadIdx.x < 32) {
        float x = part[threadIdx.x];
#pragma unroll
        for (int o = 16; o; o >>= 1) x += __shfl_xor_sync(0xffffffffu, x, o);
        if (threadIdx.x == 0) {
            g_blocksum[blockIdx.x] = x;  // plain store, no atomics
            __threadfence();
            amLast = (atomicAdd(&g_done, 1u) == NBLK - 1);
        }
    }
    __syncthreads();

    // Last block: deferred masking + global reduce + state restore.
    if (amLast) {
        const int i = threadIdx.x;                  // 256 threads
        __shared__ int fi_s[BATCH];
        if (i < BATCH) fi_s[i] = g_first_invalid[i];
        __syncthreads();

        double x = 0.0;
        // Whole blocks entirely below the row's first-invalid position.
#pragma unroll
        for (int idx = i; idx < NBLK; idx += 256) {
            const int bb = idx >> 6, k = idx & (BPR - 1);
            if ((k + 1) * TPB <= fi_s[bb]) x += (double)g_blocksum[idx];
        }
        // Boundary tokens of rows whose fi is not block-aligned (rare).
        if (i < BATCH) {
            const int fi = fi_s[i];
            if (fi < SEQ) {
                for (int s = (fi >> 6) * TPB; s < fi; s++)
                    x += (double)g_tokloss[i * SEQ + s];
            }
            g_first_invalid[i] = SEQ;               // restore for next replay
        }
        if (i == 0) g_done = 0;

        __shared__ double wsum[8];
#pragma unroll
        for (int o = 16; o; o >>= 1) x += __shfl_xor_sync(0xffffffffu, x, o);
        if ((i & 31) == 0) wsum[i >> 5] = x;
        __syncthreads();
        if (i == 0) {
            double sum = 0.0;
#pragma unroll
            for (int w = 0; w < 8; w++) sum += wsum[w];
            out[0] = (float)sum;
        }
    }
}

extern "C" void kernel_launch(void* const* d_in, const int* in_sizes, int n_in,
                              void* d_out, int out_size)
{
    const float* emit   = (const float*)d_in[0];
    const int*   target = (const int*)d_in[1];
    float*       out    = (float*)d_out;

    loss_kernel<<<NBLK, 256>>>(emit, target, out);
}

// round 12
// speedup vs baseline: 1.0738x; 1.0738x over previous
#include <cuda_runtime.h>
#include <cstdint>

#define BATCH 64
#define SEQ   4096
#define LBL   128
#define IGN   (-100)
#define NACC  512
#define TOKS_PER_BLOCK 256
#define NBLK  ((BATCH * SEQ) / TOKS_PER_BLOCK)   // 1024 loss blocks

// Statically initialized so the first (correctness) run is valid without an
// init kernel. The last loss block restores all state after each launch.
#define R8 SEQ, SEQ, SEQ, SEQ, SEQ, SEQ, SEQ, SEQ
__device__ int g_first_invalid[BATCH] = {R8, R8, R8, R8, R8, R8, R8, R8};
#undef R8
__device__ double   g_acc[NACC];       // zero-init; self-resetting
__device__ unsigned g_done = 0;        // block-completion counter; self-resetting

// Full-chip scan over target (4 MB): 512 blocks x 256 threads, 2 int4/thread.
__global__ __launch_bounds__(256) void scan_kernel(const int* __restrict__ target) {
    const int base = blockIdx.x * 512 + threadIdx.x;
    const int4* tg = reinterpret_cast<const int4*>(target);
#pragma unroll
    for (int i = 0; i < 2; i++) {
        const int token = base + i * 256;
        const int4 t = tg[token];
        if (t.x == IGN || t.y == IGN || t.z == IGN || t.w == IGN)
            atomicMin(&g_first_invalid[token >> 12], token & (SEQ - 1));
    }
}

// Software-pipelined: 8 iterations x 4 tokens per warp; loads for iteration
// i+1 issued before the exp/shfl chain of iteration i -> sustained MLP.
__global__ __launch_bounds__(256, 5) void loss_kernel(
    const float* __restrict__ emit,
    const int*   __restrict__ target,
    float*       __restrict__ out)
{
    const int warp = threadIdx.x >> 5;
    const int lane = threadIdx.x & 31;
    const int tg   = lane >> 3;          // token-in-group 0..3
    const int g    = lane & 7;           // lane-in-token 0..7

    int tok = blockIdx.x * TOKS_PER_BLOCK + warp * 32 + tg;
    const int b  = tok >> 12;            // whole block is one batch row
    const int fi = g_first_invalid[b];

    // Prologue: prefetch iteration 0.
    int nt = (g < 4) ? (target[tok * 4 + g] & (LBL - 1)) : 0;
    const float4* r = reinterpret_cast<const float4*>(emit + (size_t)tok * LBL);
    float4 n0 = r[g], n1 = r[8 + g], n2 = r[16 + g], n3 = r[24 + g];

    float prodSE = 1.0f, prodST = 1.0f;

#pragma unroll
    for (int i = 0; i < 8; i++) {
        const float4 a0 = n0, a1 = n1, a2 = n2, a3 = n3;
        const int ct  = nt;
        const int cur = tok;

        if (i < 7) {                     // prefetch iteration i+1
            tok += 4;
            nt = (g < 4) ? (target[tok * 4 + g] & (LBL - 1)) : 0;
            const float4* rn = reinterpret_cast<const float4*>(emit + (size_t)tok * LBL);
            n0 = rn[g]; n1 = rn[8 + g]; n2 = rn[16 + g]; n3 = rn[24 + g];
        }

        // sum_true gather: L1 hit on this warp's just-fetched row lines.
        float st = (g < 4) ? __expf(emit[(size_t)cur * LBL + ct]) : 0.0f;

        float se = 0.0f;
#define PASS(V)                                                     \
        {                                                           \
            const float e0 = __expf(V.x), e1 = __expf(V.y),         \
                        e2 = __expf(V.z), e3 = __expf(V.w);         \
            se += (e0 + e1) + (e2 + e3);                            \
        }
        PASS(a0) PASS(a1) PASS(a2) PASS(a3)
#undef PASS

        // Reduce within the 8-lane group.
#pragma unroll
        for (int o = 1; o <= 4; o <<= 1) {
            se += __shfl_xor_sync(0xffffffffu, se, o);
            st += __shfl_xor_sync(0xffffffffu, st, o);
        }

        // Accumulate as products: log applied once per thread-chain.
        if ((cur & (SEQ - 1)) < fi) { prodSE *= se; prodST *= st; }
    }

    __shared__ float part[32];
    __shared__ bool  amLast;
    if (g == 0)
        part[warp * 4 + tg] = __logf(prodSE) - __logf(prodST);
    __syncthreads();

    if (threadIdx.x < 32) {
        float x = part[threadIdx.x];
#pragma unroll
        for (int o = 16; o; o >>= 1) x += __shfl_xor_sync(0xffffffffu, x, o);
        if (threadIdx.x == 0) {
            atomicAdd(&g_acc[blockIdx.x & (NACC - 1)], (double)x);
            __threadfence();
            amLast = (atomicAdd(&g_done, 1u) == NBLK - 1);
        }
    }
    __syncthreads();

    // Last block: global reduce + restore all state for the next replay.
    if (amLast) {
        const int i = threadIdx.x;                     // 256 threads
        double x = g_acc[i] + g_acc[i + 256];
        g_acc[i] = 0.0;
        g_acc[i + 256] = 0.0;
        if (i < BATCH) g_first_invalid[i] = SEQ;
        if (i == 0) g_done = 0;

        __shared__ double wsum[8];
#pragma unroll
        for (int o = 16; o; o >>= 1) x += __shfl_xor_sync(0xffffffffu, x, o);
        if ((i & 31) == 0) wsum[i >> 5] = x;
        __syncthreads();
        if (i == 0) {
            double sum = 0.0;
#pragma unroll
            for (int w = 0; w < 8; w++) sum += wsum[w];
            out[0] = (float)sum;
        }
    }
}

extern "C" void kernel_launch(void* const* d_in, const int* in_sizes, int n_in,
                              void* d_out, int out_size)
{
    const float* emit   = (const float*)d_in[0];
    const int*   target = (const int*)d_in[1];
    float*       out    = (float*)d_out;

    scan_kernel<<<512, 256>>>(target);
    loss_kernel<<<NBLK, 256>>>(emit, target, out);
}

// round 13
// speedup vs baseline: 1.0760x; 1.0021x over previous
#include <cuda_runtime.h>
#include <cstdint>

#define BATCH 64
#define SEQ   4096
#define LBL   128
#define IGN   (-100)

#define TILE_TOK 128
#define NTILES   ((BATCH * SEQ) / TILE_TOK)   // 2048
#define STAGES   3
#define NBLOCK   148
#define THREADS  512

#define EMIT_BYTES  (TILE_TOK * LBL * 4)      // 65536
#define TGT_BYTES   (TILE_TOK * 4 * 4)        // 2048
#define STAGE_BYTES (EMIT_BYTES + TGT_BYTES)  // 67584
#define BAR_OFF     (STAGES * STAGE_BYTES)    // 202752
#define SMEM_TOTAL  (BAR_OFF + STAGES * 16)

// Statically initialized so the first (correctness) run is valid; last loss
// block restores all persistent state (graph-replay safe).
#define R8 SEQ, SEQ, SEQ, SEQ, SEQ, SEQ, SEQ, SEQ
__device__ int g_first_invalid[BATCH] = {R8, R8, R8, R8, R8, R8, R8, R8};
#undef R8
__device__ double   g_total = 0.0;     // self-resetting
__device__ unsigned g_done  = 0;       // self-resetting

// ---- mbarrier / bulk-copy helpers ----
__device__ __forceinline__ uint32_t s2u(const void* p) {
    return (uint32_t)__cvta_generic_to_shared(p);
}
__device__ __forceinline__ void mbar_init(uint32_t m, uint32_t cnt) {
    asm volatile("mbarrier.init.shared.b64 [%0], %1;" :: "r"(m), "r"(cnt) : "memory");
}
__device__ __forceinline__ void mbar_expect_tx(uint32_t m, uint32_t bytes) {
    asm volatile("mbarrier.arrive.expect_tx.shared.b64 _, [%0], %1;"
                 :: "r"(m), "r"(bytes) : "memory");
}
__device__ __forceinline__ void mbar_arrive(uint32_t m) {
    asm volatile("mbarrier.arrive.shared.b64 _, [%0];" :: "r"(m) : "memory");
}
__device__ __forceinline__ void mbar_wait(uint32_t m, uint32_t parity) {
    asm volatile(
        "{\n\t.reg .pred P;\n\t"
        "W%=:\n\t"
        "mbarrier.try_wait.parity.shared::cta.b64 P, [%0], %1, 0x989680;\n\t"
        "@P bra D%=;\n\t"
        "bra W%=;\n\t"
        "D%=:\n\t}"
        :: "r"(m), "r"(parity) : "memory");
}
__device__ __forceinline__ void bulk_g2s(uint32_t dst, const void* src,
                                         uint32_t bytes, uint32_t mbar) {
    asm volatile(
        "cp.async.bulk.shared::cluster.global.mbarrier::complete_tx::bytes "
        "[%0], [%1], %2, [%3];"
        :: "r"(dst), "l"(src), "r"(bytes), "r"(mbar) : "memory");
}

// Full-chip scan over target (4 MB).
__global__ __launch_bounds__(256) void scan_kernel(const int* __restrict__ target) {
    const int base = blockIdx.x * 512 + threadIdx.x;
    const int4* tg = reinterpret_cast<const int4*>(target);
#pragma unroll
    for (int i = 0; i < 2; i++) {
        const int token = base + i * 256;
        const int4 t = tg[token];
        if (t.x == IGN || t.y == IGN || t.z == IGN || t.w == IGN)
            atomicMin(&g_first_invalid[token >> 12], token & (SEQ - 1));
    }
}

// Persistent TMA-pipelined loss kernel: 148 blocks x 512 threads,
// 3-stage cp.async.bulk ring; 16 warps consume 8 tokens each per tile.
__global__ __launch_bounds__(THREADS, 1) void loss_kernel(
    const float* __restrict__ emit,
    const int*   __restrict__ target,
    float*       __restrict__ out)
{
    extern __shared__ char smem[];
    const int tid  = threadIdx.x;
    const int warp = tid >> 5;
    const int lane = tid & 31;
    const int tg   = lane >> 3;          // token-pair selector 0..3
    const int g    = lane & 7;           // lane-in-token 0..7
    const int bid  = blockIdx.x;

    const uint32_t smem_u = s2u(smem);
    const uint32_t fullb  = smem_u + BAR_OFF;       // full[s] at +s*16
    const uint32_t emptyb = smem_u + BAR_OFF + 8;   // empty[s] at +s*16+8

    if (tid == 0) {
#pragma unroll
        for (int s = 0; s < STAGES; s++) {
            mbar_init(fullb + s * 16, 1);
            mbar_init(emptyb + s * 16, THREADS);
        }
    }
    __syncthreads();

    const int myN = (NTILES - bid + NBLOCK - 1) / NBLOCK;

    int pt = 0, ps = 0, pp = 1;          // producer cursor (phase 1: first wait passes)
    int cs = 0, cp = 0;                  // consumer cursor
    float local = 0.0f;

    for (int c = 0; c < myN; c++) {
        // Top up production to keep STAGES tiles in flight.
        while (pt < myN && pt < c + STAGES) {
            if (tid == 0) {
                mbar_wait(emptyb + ps * 16, (uint32_t)pp);
                mbar_expect_tx(fullb + ps * 16, STAGE_BYTES);
                const int tile = bid + pt * NBLOCK;
                bulk_g2s(smem_u + ps * STAGE_BYTES,
                         emit + (size_t)tile * TILE_TOK * LBL,
                         EMIT_BYTES, fullb + ps * 16);
                bulk_g2s(smem_u + ps * STAGE_BYTES + EMIT_BYTES,
                         target + (size_t)tile * TILE_TOK * 4,
                         TGT_BYTES, fullb + ps * 16);
            }
            pt++;
            if (++ps == STAGES) { ps = 0; pp ^= 1; }
        }

        // Consume tile c from stage cs.
        mbar_wait(fullb + cs * 16, (uint32_t)cp);

        const int tile = bid + c * NBLOCK;
        const float* E = reinterpret_cast<const float*>(smem + cs * STAGE_BYTES);
        const int*   T = reinterpret_cast<const int*>(smem + cs * STAGE_BYTES + EMIT_BYTES);

        const int i0 = warp * 8 + tg;    // token-in-tile 0..127
        const int i1 = i0 + 4;

        const float4* r0 = reinterpret_cast<const float4*>(E + i0 * LBL);
        const float4* r1 = reinterpret_cast<const float4*>(E + i1 * LBL);
        const float4 a0 = r0[g], a1 = r0[8 + g], a2 = r0[16 + g], a3 = r0[24 + g];
        const float4 c0 = r1[g], c1 = r1[8 + g], c2 = r1[16 + g], c3 = r1[24 + g];

        float st0 = 0.0f, st1 = 0.0f;
        if (g < 4) {
            st0 = __expf(E[i0 * LBL + (T[i0 * 4 + g] & (LBL - 1))]);
            st1 = __expf(E[i1 * LBL + (T[i1 * 4 + g] & (LBL - 1))]);
        }

        float se0 = 0.0f, se1 = 0.0f;
#define PASS(ACC, V)                                                \
        {                                                           \
            const float e0 = __expf(V.x), e1 = __expf(V.y),         \
                        e2 = __expf(V.z), e3 = __expf(V.w);         \
            ACC += (e0 + e1) + (e2 + e3);                           \
        }
        PASS(se0, a0) PASS(se0, a1) PASS(se0, a2) PASS(se0, a3)
        PASS(se1, c0) PASS(se1, c1) PASS(se1, c2) PASS(se1, c3)
#undef PASS

#pragma unroll
        for (int o = 1; o <= 4; o <<= 1) {
            se0 += __shfl_xor_sync(0xffffffffu, se0, o);
            st0 += __shfl_xor_sync(0xffffffffu, st0, o);
            se1 += __shfl_xor_sync(0xffffffffu, se1, o);
            st1 += __shfl_xor_sync(0xffffffffu, st1, o);
        }

        if (g == 0) {
            const int tok0 = tile * TILE_TOK + i0;
            const int b    = tok0 >> 12;
            const int s0   = tok0 & (SEQ - 1);
            const int fi   = g_first_invalid[b];
            if (s0 + 4 < fi)             // both valid (common case): 2 logs
                local += __logf(se0 * se1) - __logf(st0 * st1);
            else if (s0 < fi)
                local += __logf(se0) - __logf(st0);
        }

        mbar_arrive(emptyb + cs * 16);   // all 512 threads
        if (++cs == STAGES) { cs = 0; cp ^= 1; }
    }

    // Block reduction + fence/counter final write.
    __shared__ float wpart[16];
    __shared__ bool  amLast;
#pragma unroll
    for (int o = 16; o; o >>= 1) local += __shfl_xor_sync(0xffffffffu, local, o);
    if (lane == 0) wpart[warp] = local;
    __syncthreads();

    if (tid == 0) {
        float bs = 0.0f;
#pragma unroll
        for (int w = 0; w < 16; w++) bs += wpart[w];
        atomicAdd(&g_total, (double)bs);
        __threadfence();
        amLast = (atomicAdd(&g_done, 1u) == NBLOCK - 1);
    }
    __syncthreads();

    if (amLast) {
        if (tid == 0) {
            out[0] = (float)g_total;
            g_total = 0.0;               // restore state for next replay
            g_done  = 0;
        }
        if (tid < BATCH) g_first_invalid[tid] = SEQ;
    }
}

extern "C" void kernel_launch(void* const* d_in, const int* in_sizes, int n_in,
                              void* d_out, int out_size)
{
    const float* emit   = (const float*)d_in[0];
    const int*   target = (const int*)d_in[1];
    float*       out    = (float*)d_out;

    static bool attr_set = false;
    if (!attr_set) {   // idempotent config, not a stream op; capture-safe
        cudaFuncSetAttribute(loss_kernel,
                             cudaFuncAttributeMaxDynamicSharedMemorySize,
                             SMEM_TOTAL);
        attr_set = true;
    }

    scan_kernel<<<512, 256>>>(target);
    loss_kernel<<<NBLOCK, THREADS, SMEM_TOTAL>>>(emit, target, out);
}

// round 15
// speedup vs baseline: 1.1491x; 1.0680x over previous
#include <cuda_runtime.h>
#include <cstdint>

#define BATCH 64
#define SEQ   4096
#define LBL   128
#define IGN   (-100)

#define TILE_TOK 128
#define NTILES   ((BATCH * SEQ) / TILE_TOK)   // 2048
#define STAGES   3
#define NBLOCK   148
#define THREADS  512

#define EMIT_BYTES  (TILE_TOK * LBL * 4)      // 65536
#define TGT_BYTES   (TILE_TOK * 4 * 4)        // 2048
#define STAGE_BYTES (EMIT_BYTES + TGT_BYTES)  // 67584
#define BAR_OFF     (STAGES * STAGE_BYTES)
#define SMEM_TOTAL  (BAR_OFF + STAGES * 16)

// Statically initialized so the first (correctness) run is valid; the last
// block restores all persistent state (graph-replay safe).
#define R8 SEQ, SEQ, SEQ, SEQ, SEQ, SEQ, SEQ, SEQ
__device__ int g_first_invalid[BATCH] = {R8, R8, R8, R8, R8, R8, R8, R8};
#undef R8
__device__ float    g_chunksum[NTILES * 16];  // overwritten every launch
__device__ double   g_total = 0.0;            // self-resetting
__device__ unsigned g_done  = 0;              // self-resetting

// ---- mbarrier / bulk-copy helpers ----
__device__ __forceinline__ uint32_t s2u(const void* p) {
    return (uint32_t)__cvta_generic_to_shared(p);
}
__device__ __forceinline__ void mbar_init(uint32_t m, uint32_t cnt) {
    asm volatile("mbarrier.init.shared.b64 [%0], %1;" :: "r"(m), "r"(cnt) : "memory");
}
__device__ __forceinline__ void mbar_expect_tx(uint32_t m, uint32_t bytes) {
    asm volatile("mbarrier.arrive.expect_tx.shared.b64 _, [%0], %1;"
                 :: "r"(m), "r"(bytes) : "memory");
}
__device__ __forceinline__ void mbar_arrive(uint32_t m) {
    asm volatile("mbarrier.arrive.shared.b64 _, [%0];" :: "r"(m) : "memory");
}
__device__ __forceinline__ void mbar_wait(uint32_t m, uint32_t parity) {
    asm volatile(
        "{\n\t.reg .pred P;\n\t"
        "W%=:\n\t"
        "mbarrier.try_wait.parity.shared::cta.b64 P, [%0], %1, 0x989680;\n\t"
        "@P bra D%=;\n\t"
        "bra W%=;\n\t"
        "D%=:\n\t}"
        :: "r"(m), "r"(parity) : "memory");
}
__device__ __forceinline__ void bulk_g2s(uint32_t dst, const void* src,
                                         uint32_t bytes, uint32_t mbar) {
    asm volatile(
        "cp.async.bulk.shared::cluster.global.mbarrier::complete_tx::bytes "
        "[%0], [%1], %2, [%3];"
        :: "r"(dst), "l"(src), "r"(bytes), "r"(mbar) : "memory");
}

// Single persistent kernel: TMA 3-stage ring; fused invalid-scan with
// locally-exact chunk masking + global correction in the last block.
__global__ __launch_bounds__(THREADS, 1) void loss_kernel(
    const float* __restrict__ emit,
    const int*   __restrict__ target,
    float*       __restrict__ out)
{
    extern __shared__ char smem[];
    const int tid  = threadIdx.x;
    const int warp = tid >> 5;
    const int lane = tid & 31;
    const int tg   = lane >> 3;          // token selector 0..3
    const int g    = lane & 7;           // lane-in-token 0..7
    const int bid  = blockIdx.x;

    const uint32_t smem_u = s2u(smem);
    const uint32_t fullb  = smem_u + BAR_OFF;
    const uint32_t emptyb = smem_u + BAR_OFF + 8;

    if (tid == 0) {
#pragma unroll
        for (int s = 0; s < STAGES; s++) {
            mbar_init(fullb + s * 16, 1);
            mbar_init(emptyb + s * 16, THREADS);
        }
    }
    __syncthreads();

    const int myN = (NTILES - bid + NBLOCK - 1) / NBLOCK;

    int pt = 0, ps = 0, pp = 1;          // producer cursor (phase 1 first pass)
    int cs = 0, cp = 0;                  // consumer cursor
    float local = 0.0f;

    for (int c = 0; c < myN; c++) {
        while (pt < myN && pt < c + STAGES) {
            if (tid == 0) {
                mbar_wait(emptyb + ps * 16, (uint32_t)pp);
                mbar_expect_tx(fullb + ps * 16, STAGE_BYTES);
                const int tile = bid + pt * NBLOCK;
                bulk_g2s(smem_u + ps * STAGE_BYTES,
                         emit + (size_t)tile * TILE_TOK * LBL,
                         EMIT_BYTES, fullb + ps * 16);
                bulk_g2s(smem_u + ps * STAGE_BYTES + EMIT_BYTES,
                         target + (size_t)tile * TILE_TOK * 4,
                         TGT_BYTES, fullb + ps * 16);
            }
            pt++;
            if (++ps == STAGES) { ps = 0; pp ^= 1; }
        }

        mbar_wait(fullb + cs * 16, (uint32_t)cp);

        const int tile = bid + c * NBLOCK;
        const float* E = reinterpret_cast<const float*>(smem + cs * STAGE_BYTES);
        const int*   T = reinterpret_cast<const int*>(smem + cs * STAGE_BYTES + EMIT_BYTES);

        const int i0 = warp * 8 + tg;    // token-in-tile
        const int i1 = i0 + 4;

        int t0r = 0, t1r = 0;
        if (g < 4) { t0r = T[i0 * 4 + g]; t1r = T[i1 * 4 + g]; }

        const float4* r0 = reinterpret_cast<const float4*>(E + i0 * LBL);
        const float4* r1 = reinterpret_cast<const float4*>(E + i1 * LBL);
        const float4 a0 = r0[g], a1 = r0[8 + g], a2 = r0[16 + g], a3 = r0[24 + g];
        const float4 c0 = r1[g], c1 = r1[8 + g], c2 = r1[16 + g], c3 = r1[24 + g];

        // Invalid detection (warp-uniform results).
        const unsigned b0 = __ballot_sync(0xffffffffu, (g < 4) && (t0r == IGN));
        const unsigned b1 = __ballot_sync(0xffffffffu, (g < 4) && (t1r == IGN));

        float st0 = 0.0f, st1 = 0.0f;
        if (g < 4) {
            st0 = __expf(E[i0 * LBL + (t0r & (LBL - 1))]);
            st1 = __expf(E[i1 * LBL + (t1r & (LBL - 1))]);
        }

        float se0 = 0.0f, se1 = 0.0f;
#define PASS(ACC, V)                                                \
        {                                                           \
            const float e0 = __expf(V.x), e1 = __expf(V.y),         \
                        e2 = __expf(V.z), e3 = __expf(V.w);         \
            ACC += (e0 + e1) + (e2 + e3);                           \
        }
        PASS(se0, a0) PASS(se0, a1) PASS(se0, a2) PASS(se0, a3)
        PASS(se1, c0) PASS(se1, c1) PASS(se1, c2) PASS(se1, c3)
#undef PASS

#pragma unroll
        for (int o = 1; o <= 4; o <<= 1) {
            se0 += __shfl_xor_sync(0xffffffffu, se0, o);
            st0 += __shfl_xor_sync(0xffffffffu, st0, o);
            se1 += __shfl_xor_sync(0xffffffffu, se1, o);
            st1 += __shfl_xor_sync(0xffffffffu, st1, o);
        }

        float v;  // chunk (8-token) masked loss sum, valid on lane 0
        if ((b0 | b1) == 0u) {
            // Common path: product across the 4 tg lanes, 2 logs per chunk.
            float pSE = se0 * se1, pST = st0 * st1;
#pragma unroll
            for (int o = 8; o <= 16; o <<= 1) {
                pSE *= __shfl_xor_sync(0xffffffffu, pSE, o);
                pST *= __shfl_xor_sync(0xffffffffu, pST, o);
            }
            v = __logf(pSE) - __logf(pST);
        } else {
            // Rare path: per-token logs with local first-IGN masking.
            unsigned inv8 = 0;
#pragma unroll
            for (int k = 0; k < 4; k++) {
                if ((b0 >> (k * 8)) & 0xFu) inv8 |= 1u << k;
                if ((b1 >> (k * 8)) & 0xFu) inv8 |= 1u << (k + 4);
            }
            const int p_min = __ffs(inv8) - 1;   // inv8 != 0 here
            float lv = 0.0f;
            if (tg < p_min)     lv += __logf(se0) - __logf(st0);
            if (tg + 4 < p_min) lv += __logf(se1) - __logf(st1);
#pragma unroll
            for (int o = 8; o <= 16; o <<= 1)
                lv += __shfl_xor_sync(0xffffffffu, lv, o);
            v = lv;
            if (lane == 0) {
                const int tok = tile * TILE_TOK + warp * 8 + p_min;
                atomicMin(&g_first_invalid[tok >> 12], tok & (SEQ - 1));
            }
        }
        if (lane == 0) {
            g_chunksum[tile * 16 + warp] = v;
            local += v;
        }

        mbar_arrive(emptyb + cs * 16);
        if (++cs == STAGES) { cs = 0; cp ^= 1; }
    }

    // Block reduction + fence/counter finalization.
    __shared__ float wpart[16];
    __shared__ bool  amLast;
#pragma unroll
    for (int o = 16; o; o >>= 1) local += __shfl_xor_sync(0xffffffffu, local, o);
    if (lane == 0) wpart[warp] = local;
    __syncthreads();

    if (tid == 0) {
        float bs = 0.0f;
#pragma unroll
        for (int w = 0; w < 16; w++) bs += wpart[w];
        atomicAdd(&g_total, (double)bs);
        __threadfence();
        amLast = (atomicAdd(&g_done, 1u) == NBLOCK - 1);
    }
    __syncthreads();

    // Last block: subtract chunks past each row's first-invalid position.
    if (amLast) {
        double corr = 0.0;
        if (tid < BATCH) {
            const int fi = g_first_invalid[tid];
            if (fi < SEQ) {
                for (int sc = (fi & ~7) + 8; sc < SEQ; sc += 8) {
                    const int tok = tid * SEQ + sc;
                    corr += (double)g_chunksum[(tok >> 7) * 16 + ((tok >> 3) & 15)];
                }
            }
            g_first_invalid[tid] = SEQ;          // restore for next replay
        }
        __shared__ double wsum[16];
#pragma unroll
        for (int o = 16; o; o >>= 1) corr += __shfl_xor_sync(0xffffffffu, corr, o);
        if (lane == 0) wsum[warp] = corr;
        __syncthreads();
        if (tid == 0) {
            double csum = 0.0;
#pragma unroll
            for (int w = 0; w < 16; w++) csum += wsum[w];
            out[0] = (float)(g_total - csum);
            g_total = 0.0;                       // restore for next replay
            g_done  = 0;
        }
    }
}

extern "C" void kernel_launch(void* const* d_in, const int* in_sizes, int n_in,
                              void* d_out, int out_size)
{
    const float* emit   = (const float*)d_in[0];
    const int*   target = (const int*)d_in[1];
    float*       out    = (float*)d_out;

    static bool attr_set = false;
    if (!attr_set) {   // idempotent config, not a stream op; capture-safe
        cudaFuncSetAttribute(loss_kernel,
                             cudaFuncAttributeMaxDynamicSharedMemorySize,
                             SMEM_TOTAL);
        attr_set = true;
    }

    loss_kernel<<<NBLOCK, THREADS, SMEM_TOTAL>>>(emit, target, out);
}